// round 7
// baseline (speedup 1.0000x reference)
#include <cuda_runtime.h>

// Live computation: out = MLP( (mean_p lidar[b,p,:]) @ wv ).
// Attention is dead (zero-pad last query row -> uniform softmax -> mean of V).
//
// Single fused launch, 1168 blocks x 256 threads (one ~wave):
//   bid [0,1024)    : lidar partial sums, batch b = bid>>6   -> g_partial
//                     each increments g_done[b]
//   bid [1024,1152) : (b,jq): prefetch weights to L2, spin on g_done[b]==64,
//                     mean fold -> bins chunk -> h1 partial  -> g_h1p
//                     each increments g_done[16+b]
//   bid [1152,1168) : b: prefetch tail weights, spin g_done[16+b]==8,
//                     h1 fold -> lrelu -> h2 -> out

#define BATCH     16
#define N_POINTS  4096
#define LIDAR_C   256
#define C4        (LIDAR_C / 4)           // 64
#define D_MODEL   1024
#define H1        128
#define SPLIT     64
#define PTS_PER_BLK (N_POINTS / SPLIT)    // 64

#define REDUCE_BLOCKS 1024
#define K2_BLOCKS     128
#define K3_BLOCKS     16
#define TOTAL_BLOCKS  (REDUCE_BLOCKS + K2_BLOCKS + K3_BLOCKS)

__device__ float4       g_partial[SPLIT * BATCH * C4];  // [64][16][64] f4
__device__ float4       g_h1p[BATCH * 8 * (H1 / 4)];    // [16][8][32] f4
__device__ unsigned int g_done[32];                     // [0..15]: reduce, [16..31]: k2

__device__ __forceinline__ void prefetch_l2(const void* p) {
    asm volatile("prefetch.global.L2 [%0];" :: "l"(p));
}

__global__ void __launch_bounds__(256)
fused_kernel(const float4* __restrict__ lidar4,   // [16][4096][64] f4
             const float4* __restrict__ wv4,      // [256][256] f4
             const float4* __restrict__ wo14,     // [1024][32] f4
             const float4* __restrict__ b14,      // [32] f4
             const float4* __restrict__ wo24,     // [128][32] f4
             const float4* __restrict__ b24,      // [32] f4
             const float4* __restrict__ wo34,     // [128][64] f4
             const float4* __restrict__ b34,      // [64] f4
             float4*       __restrict__ out4)     // [16][64] f4
{
    const int bid = blockIdx.x;
    const int tid = threadIdx.x;

    // ======================== reduce blocks ================================
    if (bid < REDUCE_BLOCKS) {
        const int b  = bid >> 6;
        const int s  = bid & 63;
        const int c4 = tid & 63;
        const int r  = tid >> 6;

        const float4* base = lidar4
            + ((size_t)b * N_POINTS + (size_t)s * PTS_PER_BLK + (size_t)r * 16) * C4 + c4;

        float4 acc = make_float4(0.f, 0.f, 0.f, 0.f);
#pragma unroll
        for (int i = 0; i < 16; ++i) {
            float4 v = __ldcs(&base[(size_t)i * C4]);
            acc.x += v.x; acc.y += v.y; acc.z += v.z; acc.w += v.w;
        }

        __shared__ float4 sp[4][C4];
        sp[r][c4] = acc;
        __syncthreads();

        if (r == 0) {
            float4 a = sp[0][c4], bb = sp[1][c4], c = sp[2][c4], d = sp[3][c4];
            float4 t;
            t.x = (a.x + bb.x) + (c.x + d.x);
            t.y = (a.y + bb.y) + (c.y + d.y);
            t.z = (a.z + bb.z) + (c.z + d.z);
            t.w = (a.w + bb.w) + (c.w + d.w);
            g_partial[((size_t)s * BATCH + b) * C4 + c4] = t;
        }

        __syncthreads();
        __threadfence();
        if (tid == 0) atomicAdd(&g_done[b], 1u);
        return;
    }

    // ======================== bins + h1-partial blocks ======================
    if (bid < REDUCE_BLOCKS + K2_BLOCKS) {
        const int idx = bid - REDUCE_BLOCKS;
        const int b   = idx >> 3;
        const int jq  = idx & 7;
        const int j4  = tid & 31;
        const int kg  = tid >> 5;                    // 0..7

        // prefetch this block's weight slices into L2 while K1 runs
        {
            // wv chunk: rows 0..255, cols [jq*32, jq*32+32) f4 -> 4 lines/row
            const float4* wvb = wv4 + (size_t)jq * 32;
            prefetch_l2(wvb + (size_t)tid * 256 + 0);
            prefetch_l2(wvb + (size_t)tid * 256 + 8);
            prefetch_l2(wvb + (size_t)tid * 256 + 16);
            prefetch_l2(wvb + (size_t)tid * 256 + 24);
            // wo1 slice: rows [jq*128, jq*128+128), 32 f4/row -> 512 lines
            const float4* w1b = wo14 + (size_t)jq * 128 * 32;
            prefetch_l2(w1b + (size_t)tid * 16);
            prefetch_l2(w1b + (size_t)tid * 16 + 8);
        }

        if (tid == 0) {
            volatile unsigned int* p = &g_done[b];
            while (*p < 64u) __nanosleep(64);
        }
        __syncthreads();
        __threadfence();

        __shared__ float4 sp[4][C4];
        __shared__ float  s_mean[LIDAR_C];
        __shared__ float  s_binsc[128];
        __shared__ float4 s_red[8][32];

        // ---- fold 64 partials -> mean -------------------------------------
        {
            const int c4 = tid & 63;
            const int sg = tid >> 6;                 // 0..3
            const float4* p = g_partial + (size_t)b * C4 + c4;
            float4 acc = make_float4(0.f, 0.f, 0.f, 0.f);
#pragma unroll
            for (int i = 0; i < 16; ++i) {
                float4 v = p[(size_t)(sg * 16 + i) * (BATCH * C4)];
                acc.x += v.x; acc.y += v.y; acc.z += v.z; acc.w += v.w;
            }
            sp[sg][c4] = acc;
        }
        __syncthreads();
        if (tid < C4) {
            float4 a = sp[0][tid], bb = sp[1][tid], c = sp[2][tid], d = sp[3][tid];
            const float inv = 1.0f / (float)N_POINTS;
            s_mean[tid * 4 + 0] = ((a.x + bb.x) + (c.x + d.x)) * inv;
            s_mean[tid * 4 + 1] = ((a.y + bb.y) + (c.y + d.y)) * inv;
            s_mean[tid * 4 + 2] = ((a.z + bb.z) + (c.z + d.z)) * inv;
            s_mean[tid * 4 + 3] = ((a.w + bb.w) + (c.w + d.w)) * inv;
        }
        __syncthreads();

        // ---- bins chunk: 32 j4 x 8 kg of 32 k ------------------------------
        {
            const float4* w = wv4 + (size_t)(kg * 32) * 256 + jq * 32 + j4;
            const float*  m = s_mean + kg * 32;
            float4 acc = make_float4(0.f, 0.f, 0.f, 0.f);
#pragma unroll 8
            for (int k = 0; k < 32; ++k) {
                float4 v = __ldg(&w[(size_t)k * 256]);
                float  s = m[k];
                acc.x += s * v.x; acc.y += s * v.y; acc.z += s * v.z; acc.w += s * v.w;
            }
            s_red[kg][j4] = acc;
        }
        __syncthreads();
        if (tid < 32) {
            float4 acc = make_float4(0.f, 0.f, 0.f, 0.f);
#pragma unroll
            for (int g = 0; g < 8; ++g) {
                float4 v = s_red[g][tid];
                acc.x += v.x; acc.y += v.y; acc.z += v.z; acc.w += v.w;
            }
            s_binsc[tid * 4 + 0] = acc.x;
            s_binsc[tid * 4 + 1] = acc.y;
            s_binsc[tid * 4 + 2] = acc.z;
            s_binsc[tid * 4 + 3] = acc.w;
        }
        __syncthreads();

        // ---- h1 partial: 32 j4 x 8 kg of 16 k ------------------------------
        {
            const float4* w = wo14 + ((size_t)jq * 128 + kg * 16) * 32 + j4;
            const float*  m = s_binsc + kg * 16;
            float4 acc = make_float4(0.f, 0.f, 0.f, 0.f);
#pragma unroll
            for (int k = 0; k < 16; ++k) {
                float4 v = __ldg(&w[(size_t)k * 32]);
                float  s = m[k];
                acc.x += s * v.x; acc.y += s * v.y; acc.z += s * v.z; acc.w += s * v.w;
            }
            s_red[kg][j4] = acc;
        }
        __syncthreads();
        if (tid < 32) {
            float4 acc = make_float4(0.f, 0.f, 0.f, 0.f);
#pragma unroll
            for (int g = 0; g < 8; ++g) {
                float4 v = s_red[g][tid];
                acc.x += v.x; acc.y += v.y; acc.z += v.z; acc.w += v.w;
            }
            g_h1p[((size_t)b * 8 + jq) * 32 + tid] = acc;
        }

        __syncthreads();
        __threadfence();
        if (tid == 0) atomicAdd(&g_done[16 + b], 1u);
        return;
    }

    // ======================== head blocks ===================================
    {
        const int b = bid - (REDUCE_BLOCKS + K2_BLOCKS);

        // prefetch tail weights (wo2 16KB, wo3 32KB, biases) into L2
        {
            prefetch_l2(wo24 + (size_t)tid * 4);
            prefetch_l2(wo34 + (size_t)tid * 8);
            prefetch_l2(wo34 + (size_t)tid * 8 + 1024);
            if (tid < 16) {
                prefetch_l2(b14 + tid * 2);
                prefetch_l2(b24 + tid * 2);
            }
            if (tid < 32) prefetch_l2(b34 + tid * 2);
        }

        if (tid == 0) {
            volatile unsigned int* p = &g_done[16 + b];
            while (*p < 8u) __nanosleep(64);
        }
        __syncthreads();
        __threadfence();

        __shared__ float4 s_p[256];
        __shared__ float  s_h1[H1];
        __shared__ float  s_h2[H1];

        s_p[tid] = g_h1p[(size_t)b * 256 + tid];
        __syncthreads();

        // h1 = lrelu(sum_g partials + b1)
        if (tid < 32) {
            float4 acc = __ldg(&b14[tid]);
#pragma unroll
            for (int g = 0; g < 8; ++g) {
                float4 v = s_p[g * 32 + tid];
                acc.x += v.x; acc.y += v.y; acc.z += v.z; acc.w += v.w;
            }
            s_h1[tid * 4 + 0] = (acc.x > 0.f) ? acc.x : 0.01f * acc.x;
            s_h1[tid * 4 + 1] = (acc.y > 0.f) ? acc.y : 0.01f * acc.y;
            s_h1[tid * 4 + 2] = (acc.z > 0.f) ? acc.z : 0.01f * acc.z;
            s_h1[tid * 4 + 3] = (acc.w > 0.f) ? acc.w : 0.01f * acc.w;
        }
        __syncthreads();

        // h2 = lrelu(h1 @ wo2 + b2): 32 j4 x 8 kg of 16 k
        {
            const int j4 = tid & 31;
            const int kg = tid >> 5;
            const float4* w = wo24 + (size_t)(kg * 16) * 32 + j4;
            const float*  m = s_h1 + kg * 16;
            float4 acc = make_float4(0.f, 0.f, 0.f, 0.f);
#pragma unroll
            for (int k = 0; k < 16; ++k) {
                float4 v = __ldg(&w[(size_t)k * 32]);
                float  s = m[k];
                acc.x += s * v.x; acc.y += s * v.y; acc.z += s * v.z; acc.w += s * v.w;
            }
            __syncthreads();
            s_p[kg * 32 + j4] = acc;
        }
        __syncthreads();
        if (tid < 32) {
            float4 acc = __ldg(&b24[tid]);
#pragma unroll
            for (int g = 0; g < 8; ++g) {
                float4 v = s_p[g * 32 + tid];
                acc.x += v.x; acc.y += v.y; acc.z += v.z; acc.w += v.w;
            }
            s_h2[tid * 4 + 0] = (acc.x > 0.f) ? acc.x : 0.01f * acc.x;
            s_h2[tid * 4 + 1] = (acc.y > 0.f) ? acc.y : 0.01f * acc.y;
            s_h2[tid * 4 + 2] = (acc.z > 0.f) ? acc.z : 0.01f * acc.z;
            s_h2[tid * 4 + 3] = (acc.w > 0.f) ? acc.w : 0.01f * acc.w;
        }
        __syncthreads();

        // out = h2 @ wo3 + b3: 64 j4 x 4 kg of 32 k
        {
            const int j4 = tid & 63;
            const int kg = tid >> 6;
            const float4* w = wo34 + (size_t)(kg * 32) * 64 + j4;
            const float*  m = s_h2 + kg * 32;
            float4 acc = make_float4(0.f, 0.f, 0.f, 0.f);
#pragma unroll 8
            for (int k = 0; k < 32; ++k) {
                float4 v = __ldg(&w[(size_t)k * 64]);
                float  s = m[k];
                acc.x += s * v.x; acc.y += s * v.y; acc.z += s * v.z; acc.w += s * v.w;
            }
            __syncthreads();
            s_p[kg * 64 + j4] = acc;
        }
        __syncthreads();
        if (tid < 64) {
            float4 acc = __ldg(&b34[tid]);
#pragma unroll
            for (int g = 0; g < 4; ++g) {
                float4 v = s_p[g * 64 + tid];
                acc.x += v.x; acc.y += v.y; acc.z += v.z; acc.w += v.w;
            }
            out4[(size_t)b * 64 + tid] = acc;
        }
    }
}

// ---------------------------------------------------------------------------
// Inputs: 0 feature, 1 lidar, 2 conv1_w, 3 conv2_w, 4 wq, 5 wk, 6 wv,
//         7 wo1, 8 b1, 9 wo2, 10 b2, 11 wo3, 12 b3
// ---------------------------------------------------------------------------
extern "C" void kernel_launch(void* const* d_in, const int* in_sizes, int n_in,
                              void* d_out, int out_size)
{
    const float4* lidar4 = (const float4*)d_in[1];
    const float4* wv4    = (const float4*)d_in[6];
    const float4* wo14   = (const float4*)d_in[7];
    const float4* b14    = (const float4*)d_in[8];
    const float4* wo24   = (const float4*)d_in[9];
    const float4* b24    = (const float4*)d_in[10];
    const float4* wo34   = (const float4*)d_in[11];
    const float4* b34    = (const float4*)d_in[12];
    float4* out4 = (float4*)d_out;

    void* sync_addr = nullptr;
    cudaGetSymbolAddress(&sync_addr, g_done);
    cudaMemsetAsync(sync_addr, 0, 32 * sizeof(unsigned int));

    fused_kernel<<<TOTAL_BLOCKS, 256>>>(lidar4, wv4, wo14, b14,
                                        wo24, b24, wo34, b34, out4);
}

// round 8
// speedup vs baseline: 1.3277x; 1.3277x over previous
#include <cuda_runtime.h>

// Live computation: out = MLP( (mean_p lidar[b,p,:]) @ wv ).
// Attention is dead (zero-pad last query row -> uniform softmax -> mean of V).
//
// 2-kernel chain:
//   K1 reduce  : lidar partial column sums           grid (16,32) x 256
//                (64-reg budget -> deep load batching; single wave)
//   K2 bins+h1 : mean fold; bins chunk = mean@wv[:,jq]; h1 partial.
//                The LAST block per batch (atomic counter) runs the tail
//                (h1 fold -> lrelu -> h2 -> out) inline. Deterministic:
//                fixed-order gmem folds regardless of which block is last.

#define BATCH     16
#define N_POINTS  4096
#define LIDAR_C   256
#define C4        (LIDAR_C / 4)           // 64
#define D_MODEL   1024
#define H1        128
#define SPLIT     32
#define PTS_PER_BLK (N_POINTS / SPLIT)    // 128

__device__ float4       g_partial[SPLIT * BATCH * C4];  // [32][16][64] f4
__device__ float4       g_h1p[BATCH * 8 * (H1 / 4)];    // [16][8][32] f4
__device__ unsigned int g_k2done[BATCH];                // zero-init, self-reset

// ---------------------------------------------------------------------------
// K1: partial column sums of lidar (67 MB stream). 4 blocks/SM (64 regs) so
// ptxas can front-batch ~8-12 LDG.128 per warp; 4 independent accumulators.
// ---------------------------------------------------------------------------
__global__ void __launch_bounds__(256, 4)
lidar_reduce_kernel(const float4* __restrict__ lidar4)
{
    const int b  = blockIdx.x;
    const int s  = blockIdx.y;
    const int c4 = threadIdx.x & 63;
    const int r  = threadIdx.x >> 6;           // 0..3, 32 rows each

    const float4* base = lidar4
        + ((size_t)b * N_POINTS + (size_t)s * PTS_PER_BLK + (size_t)r * 32) * C4 + c4;

    float4 a0 = make_float4(0.f, 0.f, 0.f, 0.f);
    float4 a1 = make_float4(0.f, 0.f, 0.f, 0.f);
    float4 a2 = make_float4(0.f, 0.f, 0.f, 0.f);
    float4 a3 = make_float4(0.f, 0.f, 0.f, 0.f);
#pragma unroll
    for (int i = 0; i < 32; i += 4) {
        float4 v0 = __ldcs(&base[(size_t)(i + 0) * C4]);
        float4 v1 = __ldcs(&base[(size_t)(i + 1) * C4]);
        float4 v2 = __ldcs(&base[(size_t)(i + 2) * C4]);
        float4 v3 = __ldcs(&base[(size_t)(i + 3) * C4]);
        a0.x += v0.x; a0.y += v0.y; a0.z += v0.z; a0.w += v0.w;
        a1.x += v1.x; a1.y += v1.y; a1.z += v1.z; a1.w += v1.w;
        a2.x += v2.x; a2.y += v2.y; a2.z += v2.z; a2.w += v2.w;
        a3.x += v3.x; a3.y += v3.y; a3.z += v3.z; a3.w += v3.w;
    }
    float4 acc;
    acc.x = (a0.x + a1.x) + (a2.x + a3.x);
    acc.y = (a0.y + a1.y) + (a2.y + a3.y);
    acc.z = (a0.z + a1.z) + (a2.z + a3.z);
    acc.w = (a0.w + a1.w) + (a2.w + a3.w);

    __shared__ float4 sp[4][C4];
    sp[r][c4] = acc;
    __syncthreads();

    if (r == 0) {
        float4 a = sp[0][c4], bb = sp[1][c4], c = sp[2][c4], d = sp[3][c4];
        float4 t;
        t.x = (a.x + bb.x) + (c.x + d.x);
        t.y = (a.y + bb.y) + (c.y + d.y);
        t.z = (a.z + bb.z) + (c.z + d.z);
        t.w = (a.w + bb.w) + (c.w + d.w);
        g_partial[((size_t)s * BATCH + b) * C4 + c4] = t;
    }
}

// ---------------------------------------------------------------------------
// K2: per (batch, j-chunk): fold partials -> mean; bins_chunk = mean @ wv
// cols [jq*128,+128); h1 partial = bins_chunk @ wo1[chunk rows]. Last block
// per batch runs the tail MLP inline.
// ---------------------------------------------------------------------------
__global__ void __launch_bounds__(256)
bins_h1_kernel(const float4* __restrict__ wv4,     // [256][256] f4
               const float4* __restrict__ wo14,    // [1024][32] f4
               const float4* __restrict__ b14,     // [32] f4
               const float4* __restrict__ wo24,    // [128][32] f4
               const float4* __restrict__ b24,     // [32] f4
               const float4* __restrict__ wo34,    // [128][64] f4
               const float4* __restrict__ b34,     // [64] f4
               float4*       __restrict__ out4)    // [16][64] f4
{
    const int b   = blockIdx.x;
    const int jq  = blockIdx.y;                    // 0..7
    const int tid = threadIdx.x;
    const int j4  = tid & 31;
    const int kg  = tid >> 5;                      // 0..7

    __shared__ float4 sp[4][C4];
    __shared__ float  s_mean[LIDAR_C];
    __shared__ float  s_binsc[128];
    __shared__ float4 s_red[8][32];
    __shared__ int    s_last;

    // ---- fold 32 partials -> mean -----------------------------------------
    {
        const int c4 = tid & 63;
        const int sg = tid >> 6;                   // 0..3, 8 partials each
        const float4* p = g_partial + (size_t)b * C4 + c4;
        float4 acc = make_float4(0.f, 0.f, 0.f, 0.f);
#pragma unroll
        for (int i = 0; i < 8; ++i) {
            float4 v = p[(size_t)(sg * 8 + i) * (BATCH * C4)];
            acc.x += v.x; acc.y += v.y; acc.z += v.z; acc.w += v.w;
        }
        sp[sg][c4] = acc;
    }
    __syncthreads();
    if (tid < C4) {
        float4 a = sp[0][tid], bb = sp[1][tid], c = sp[2][tid], d = sp[3][tid];
        const float inv = 1.0f / (float)N_POINTS;
        s_mean[tid * 4 + 0] = ((a.x + bb.x) + (c.x + d.x)) * inv;
        s_mean[tid * 4 + 1] = ((a.y + bb.y) + (c.y + d.y)) * inv;
        s_mean[tid * 4 + 2] = ((a.z + bb.z) + (c.z + d.z)) * inv;
        s_mean[tid * 4 + 3] = ((a.w + bb.w) + (c.w + d.w)) * inv;
    }
    __syncthreads();

    // ---- bins chunk: 32 j4 x 8 kg of 32 k ----------------------------------
    {
        const float4* w = wv4 + (size_t)(kg * 32) * 256 + jq * 32 + j4;
        const float*  m = s_mean + kg * 32;
        float4 acc = make_float4(0.f, 0.f, 0.f, 0.f);
#pragma unroll 8
        for (int k = 0; k < 32; ++k) {
            float4 v = __ldg(&w[(size_t)k * 256]);
            float  s = m[k];
            acc.x += s * v.x; acc.y += s * v.y; acc.z += s * v.z; acc.w += s * v.w;
        }
        s_red[kg][j4] = acc;
    }
    __syncthreads();
    if (tid < 32) {
        float4 acc = make_float4(0.f, 0.f, 0.f, 0.f);
#pragma unroll
        for (int g = 0; g < 8; ++g) {
            float4 v = s_red[g][tid];
            acc.x += v.x; acc.y += v.y; acc.z += v.z; acc.w += v.w;
        }
        s_binsc[tid * 4 + 0] = acc.x;
        s_binsc[tid * 4 + 1] = acc.y;
        s_binsc[tid * 4 + 2] = acc.z;
        s_binsc[tid * 4 + 3] = acc.w;
    }
    __syncthreads();

    // ---- h1 partial: 32 j4 x 8 kg of 16 k ----------------------------------
    {
        const float4* w = wo14 + ((size_t)jq * 128 + kg * 16) * 32 + j4;
        const float*  m = s_binsc + kg * 16;
        float4 acc = make_float4(0.f, 0.f, 0.f, 0.f);
#pragma unroll
        for (int k = 0; k < 16; ++k) {
            float4 v = __ldg(&w[(size_t)k * 32]);
            float  s = m[k];
            acc.x += s * v.x; acc.y += s * v.y; acc.z += s * v.z; acc.w += s * v.w;
        }
        s_red[kg][j4] = acc;
    }
    __syncthreads();
    if (tid < 32) {
        float4 acc = make_float4(0.f, 0.f, 0.f, 0.f);
#pragma unroll
        for (int g = 0; g < 8; ++g) {
            float4 v = s_red[g][tid];
            acc.x += v.x; acc.y += v.y; acc.z += v.z; acc.w += v.w;
        }
        g_h1p[((size_t)b * 8 + jq) * 32 + tid] = acc;
    }
    __syncthreads();

    // ---- last block per batch runs the tail MLP ----------------------------
    __threadfence();
    if (tid == 0) {
        unsigned int old = atomicAdd(&g_k2done[b], 1u);
        s_last = (old == 7u) ? 1 : 0;
    }
    __syncthreads();
    if (!s_last) return;
    __threadfence();   // acquire: make all 8 blocks' g_h1p writes visible

    // reuse s_red (flat 256 f4) as the working buffer
    float4* s_p = &s_red[0][0];
    __shared__ float s_h1[H1];
    __shared__ float s_h2[H1];

    s_p[tid] = g_h1p[(size_t)b * 256 + tid];
    __syncthreads();

    // h1 = lrelu(sum_g partials + b1)
    if (tid < 32) {
        float4 acc = __ldg(&b14[tid]);
#pragma unroll
        for (int g = 0; g < 8; ++g) {
            float4 v = s_p[g * 32 + tid];
            acc.x += v.x; acc.y += v.y; acc.z += v.z; acc.w += v.w;
        }
        s_h1[tid * 4 + 0] = (acc.x > 0.f) ? acc.x : 0.01f * acc.x;
        s_h1[tid * 4 + 1] = (acc.y > 0.f) ? acc.y : 0.01f * acc.y;
        s_h1[tid * 4 + 2] = (acc.z > 0.f) ? acc.z : 0.01f * acc.z;
        s_h1[tid * 4 + 3] = (acc.w > 0.f) ? acc.w : 0.01f * acc.w;
    }
    __syncthreads();

    // h2 = lrelu(h1 @ wo2 + b2): 32 j4 x 8 kg of 16 k
    {
        const float4* w = wo24 + (size_t)(kg * 16) * 32 + j4;
        const float*  m = s_h1 + kg * 16;
        float4 acc = make_float4(0.f, 0.f, 0.f, 0.f);
#pragma unroll
        for (int k = 0; k < 16; ++k) {
            float4 v = __ldg(&w[(size_t)k * 32]);
            float  s = m[k];
            acc.x += s * v.x; acc.y += s * v.y; acc.z += s * v.z; acc.w += s * v.w;
        }
        __syncthreads();
        s_p[kg * 32 + j4] = acc;
    }
    __syncthreads();
    if (tid < 32) {
        float4 acc = __ldg(&b24[tid]);
#pragma unroll
        for (int g = 0; g < 8; ++g) {
            float4 v = s_p[g * 32 + tid];
            acc.x += v.x; acc.y += v.y; acc.z += v.z; acc.w += v.w;
        }
        s_h2[tid * 4 + 0] = (acc.x > 0.f) ? acc.x : 0.01f * acc.x;
        s_h2[tid * 4 + 1] = (acc.y > 0.f) ? acc.y : 0.01f * acc.y;
        s_h2[tid * 4 + 2] = (acc.z > 0.f) ? acc.z : 0.01f * acc.z;
        s_h2[tid * 4 + 3] = (acc.w > 0.f) ? acc.w : 0.01f * acc.w;
    }
    __syncthreads();

    // out = h2 @ wo3 + b3: 64 j4o x 4 kgo of 32 k
    {
        const int j4o = tid & 63;
        const int kgo = tid >> 6;                 // 0..3
        const float4* w = wo34 + (size_t)(kgo * 32) * 64 + j4o;
        const float*  m = s_h2 + kgo * 32;
        float4 acc = make_float4(0.f, 0.f, 0.f, 0.f);
#pragma unroll 8
        for (int k = 0; k < 32; ++k) {
            float4 v = __ldg(&w[(size_t)k * 64]);
            float  s = m[k];
            acc.x += s * v.x; acc.y += s * v.y; acc.z += s * v.z; acc.w += s * v.w;
        }
        __syncthreads();
        s_p[kgo * 64 + j4o] = acc;
    }
    __syncthreads();
    if (tid < 64) {
        float4 acc = __ldg(&b34[tid]);
#pragma unroll
        for (int g = 0; g < 4; ++g) {
            float4 v = s_p[g * 64 + tid];
            acc.x += v.x; acc.y += v.y; acc.z += v.z; acc.w += v.w;
        }
        out4[(size_t)b * 64 + tid] = acc;
    }

    // self-reset counter for the next graph replay (all 8 adds already done)
    if (tid == 0) g_k2done[b] = 0u;
}

// ---------------------------------------------------------------------------
// Inputs: 0 feature, 1 lidar, 2 conv1_w, 3 conv2_w, 4 wq, 5 wk, 6 wv,
//         7 wo1, 8 b1, 9 wo2, 10 b2, 11 wo3, 12 b3
// ---------------------------------------------------------------------------
extern "C" void kernel_launch(void* const* d_in, const int* in_sizes, int n_in,
                              void* d_out, int out_size)
{
    const float4* lidar4 = (const float4*)d_in[1];
    const float4* wv4    = (const float4*)d_in[6];
    const float4* wo14   = (const float4*)d_in[7];
    const float4* b14    = (const float4*)d_in[8];
    const float4* wo24   = (const float4*)d_in[9];
    const float4* b24    = (const float4*)d_in[10];
    const float4* wo34   = (const float4*)d_in[11];
    const float4* b34    = (const float4*)d_in[12];
    float4* out4 = (float4*)d_out;

    lidar_reduce_kernel<<<dim3(BATCH, SPLIT), 256>>>(lidar4);
    bins_h1_kernel<<<dim3(BATCH, 8), 256>>>(wv4, wo14, b14,
                                            wo24, b24, wo34, b34, out4);
}

// round 9
// speedup vs baseline: 1.5928x; 1.1997x over previous
#include <cuda_runtime.h>

// Live computation: out = MLP( (mean_p lidar[b,p,:]) @ wv ).
// Attention is dead (zero-pad last query row -> uniform softmax -> mean of V).
//
// 3-kernel chain (R6 skeleton, proven 20.0us):
//   K1 reduce  : lidar partial column sums   grid 1024+14 x 256
//                (+14 prefetch-and-exit blocks that pull all downstream
//                 weights into L2 under the shadow of the DRAM stream)
//   K2 bins+h1 : mean fold; bins chunk = mean@wv[:,jq]; h1 partial
//   K3 head    : fold h1 partials -> lrelu -> h2 -> out

#define BATCH     16
#define N_POINTS  4096
#define LIDAR_C   256
#define C4        (LIDAR_C / 4)           // 64
#define D_MODEL   1024
#define H1        128
#define SPLIT     64
#define PTS_PER_BLK (N_POINTS / SPLIT)    // 64

#define REDUCE_BLOCKS (BATCH * SPLIT)     // 1024
#define PF_BLOCKS     14

__device__ float4 g_partial[SPLIT * BATCH * C4];   // [64][16][64] f4 = 1 MB
__device__ float4 g_h1p[BATCH * 8 * (H1 / 4)];     // [16][8][32] f4

__device__ __forceinline__ void prefetch_l2(const void* p) {
    asm volatile("prefetch.global.L2 [%0];" :: "l"(p));
}

// ---------------------------------------------------------------------------
// K1: partial column sums of lidar (DRAM-bound, 67 MB) + weight prefetch.
// ---------------------------------------------------------------------------
__global__ void __launch_bounds__(256)
lidar_reduce_kernel(const float4* __restrict__ lidar4,
                    const char*   __restrict__ wv_b,    // 1 MB
                    const char*   __restrict__ wo1_b,   // 512 KB
                    const char*   __restrict__ wo2_b,   // 64 KB
                    const char*   __restrict__ wo3_b)   // 128 KB
{
    const int bid = blockIdx.x;
    const int tid = threadIdx.x;

    if (bid >= REDUCE_BLOCKS) {
        // ---- prefetch-and-exit blocks: warm L2 with downstream weights ----
        const int pb = bid - REDUCE_BLOCKS;       // 0..13
        if (pb < 8) {
            // wv: 8192 lines; 8 blocks x 256 thr x 4 lines
            const char* p = wv_b + ((size_t)pb * 256 + tid) * 512;
            prefetch_l2(p);       prefetch_l2(p + 128);
            prefetch_l2(p + 256); prefetch_l2(p + 384);
        } else if (pb < 12) {
            // wo1: 4096 lines; 4 blocks x 256 thr x 4 lines
            const char* p = wo1_b + ((size_t)(pb - 8) * 256 + tid) * 512;
            prefetch_l2(p);       prefetch_l2(p + 128);
            prefetch_l2(p + 256); prefetch_l2(p + 384);
        } else if (pb == 12) {
            // wo3: 1024 lines; 256 thr x 4 lines
            const char* p = wo3_b + (size_t)tid * 512;
            prefetch_l2(p);       prefetch_l2(p + 128);
            prefetch_l2(p + 256); prefetch_l2(p + 384);
        } else {
            // wo2: 512 lines; 256 thr x 2 lines
            const char* p = wo2_b + (size_t)tid * 256;
            prefetch_l2(p);       prefetch_l2(p + 128);
        }
        return;
    }

    const int b  = bid >> 6;
    const int s  = bid & 63;
    const int c4 = tid & 63;
    const int r  = tid >> 6;

    const float4* base = lidar4
        + ((size_t)b * N_POINTS + (size_t)s * PTS_PER_BLK + (size_t)r * 16) * C4 + c4;

    float4 acc = make_float4(0.f, 0.f, 0.f, 0.f);
#pragma unroll
    for (int i = 0; i < 16; ++i) {
        float4 v = __ldcs(&base[(size_t)i * C4]);
        acc.x += v.x; acc.y += v.y; acc.z += v.z; acc.w += v.w;
    }

    __shared__ float4 sp[4][C4];
    sp[r][c4] = acc;
    __syncthreads();

    if (r == 0) {
        float4 a = sp[0][c4], bb = sp[1][c4], c = sp[2][c4], d = sp[3][c4];
        float4 t;
        t.x = (a.x + bb.x) + (c.x + d.x);
        t.y = (a.y + bb.y) + (c.y + d.y);
        t.z = (a.z + bb.z) + (c.z + d.z);
        t.w = (a.w + bb.w) + (c.w + d.w);
        g_partial[((size_t)s * BATCH + b) * C4 + c4] = t;
    }
}

// ---------------------------------------------------------------------------
// K2: per (batch, j-chunk): fold partials -> mean; bins_chunk = mean @ wv
// cols [jq*128,+128); h1 partial = bins_chunk @ wo1[chunk rows].
// ---------------------------------------------------------------------------
__global__ void __launch_bounds__(256)
bins_h1_kernel(const float4* __restrict__ wv4,     // [256][256] f4
               const float4* __restrict__ wo14)    // [1024][32] f4
{
    const int b   = blockIdx.x;
    const int jq  = blockIdx.y;                    // 0..7
    const int tid = threadIdx.x;
    const int j4  = tid & 31;
    const int kg  = tid >> 5;                      // 0..7

    __shared__ float4 sp[4][C4];
    __shared__ float  s_mean[LIDAR_C];
    __shared__ float  s_binsc[128];
    __shared__ float4 s_red[8][32];

    // ---- fold 64 partials -> mean -----------------------------------------
    {
        const int c4 = tid & 63;
        const int sg = tid >> 6;                   // 0..3
        const float4* p = g_partial + (size_t)b * C4 + c4;
        float4 acc = make_float4(0.f, 0.f, 0.f, 0.f);
#pragma unroll
        for (int i = 0; i < 16; ++i) {
            float4 v = p[(size_t)(sg * 16 + i) * (BATCH * C4)];
            acc.x += v.x; acc.y += v.y; acc.z += v.z; acc.w += v.w;
        }
        sp[sg][c4] = acc;
    }
    __syncthreads();
    if (tid < C4) {
        float4 a = sp[0][tid], bb = sp[1][tid], c = sp[2][tid], d = sp[3][tid];
        const float inv = 1.0f / (float)N_POINTS;
        s_mean[tid * 4 + 0] = ((a.x + bb.x) + (c.x + d.x)) * inv;
        s_mean[tid * 4 + 1] = ((a.y + bb.y) + (c.y + d.y)) * inv;
        s_mean[tid * 4 + 2] = ((a.z + bb.z) + (c.z + d.z)) * inv;
        s_mean[tid * 4 + 3] = ((a.w + bb.w) + (c.w + d.w)) * inv;
    }
    __syncthreads();

    // ---- bins chunk: 32 j4 x 8 kg of 32 k ----------------------------------
    {
        const float4* w = wv4 + (size_t)(kg * 32) * 256 + jq * 32 + j4;
        const float*  m = s_mean + kg * 32;
        float4 acc = make_float4(0.f, 0.f, 0.f, 0.f);
#pragma unroll 8
        for (int k = 0; k < 32; ++k) {
            float4 v = __ldg(&w[(size_t)k * 256]);
            float  s = m[k];
            acc.x += s * v.x; acc.y += s * v.y; acc.z += s * v.z; acc.w += s * v.w;
        }
        s_red[kg][j4] = acc;
    }
    __syncthreads();
    if (tid < 32) {
        float4 acc = make_float4(0.f, 0.f, 0.f, 0.f);
#pragma unroll
        for (int g = 0; g < 8; ++g) {
            float4 v = s_red[g][tid];
            acc.x += v.x; acc.y += v.y; acc.z += v.z; acc.w += v.w;
        }
        s_binsc[tid * 4 + 0] = acc.x;
        s_binsc[tid * 4 + 1] = acc.y;
        s_binsc[tid * 4 + 2] = acc.z;
        s_binsc[tid * 4 + 3] = acc.w;
    }
    __syncthreads();

    // ---- h1 partial: 32 j4 x 8 kg of 16 k ----------------------------------
    {
        const float4* w = wo14 + ((size_t)jq * 128 + kg * 16) * 32 + j4;
        const float*  m = s_binsc + kg * 16;
        float4 acc = make_float4(0.f, 0.f, 0.f, 0.f);
#pragma unroll
        for (int k = 0; k < 16; ++k) {
            float4 v = __ldg(&w[(size_t)k * 32]);
            float  s = m[k];
            acc.x += s * v.x; acc.y += s * v.y; acc.z += s * v.z; acc.w += s * v.w;
        }
        s_red[kg][j4] = acc;
    }
    __syncthreads();
    if (tid < 32) {
        float4 acc = make_float4(0.f, 0.f, 0.f, 0.f);
#pragma unroll
        for (int g = 0; g < 8; ++g) {
            float4 v = s_red[g][tid];
            acc.x += v.x; acc.y += v.y; acc.z += v.z; acc.w += v.w;
        }
        g_h1p[((size_t)b * 8 + jq) * 32 + tid] = acc;
    }
}

// ---------------------------------------------------------------------------
// K3: per-batch tail: fold h1 partials + b1 -> lrelu -> h2 -> out.
// ---------------------------------------------------------------------------
__global__ void __launch_bounds__(256)
head_kernel(const float4* __restrict__ b14,    // [32] f4
            const float4* __restrict__ wo24,   // [128][32] f4
            const float4* __restrict__ b24,    // [32] f4
            const float4* __restrict__ wo34,   // [128][64] f4
            const float4* __restrict__ b34,    // [64] f4
            float4*       __restrict__ out4)   // [16][64] f4
{
    const int b   = blockIdx.x;
    const int tid = threadIdx.x;

    __shared__ float4 s_p[256];
    __shared__ float  s_h1[H1];
    __shared__ float  s_h2[H1];

    s_p[tid] = g_h1p[(size_t)b * 256 + tid];
    __syncthreads();

    // h1 = lrelu(sum_g partials + b1)
    if (tid < 32) {
        float4 acc = __ldg(&b14[tid]);
#pragma unroll
        for (int g = 0; g < 8; ++g) {
            float4 v = s_p[g * 32 + tid];
            acc.x += v.x; acc.y += v.y; acc.z += v.z; acc.w += v.w;
        }
        s_h1[tid * 4 + 0] = (acc.x > 0.f) ? acc.x : 0.01f * acc.x;
        s_h1[tid * 4 + 1] = (acc.y > 0.f) ? acc.y : 0.01f * acc.y;
        s_h1[tid * 4 + 2] = (acc.z > 0.f) ? acc.z : 0.01f * acc.z;
        s_h1[tid * 4 + 3] = (acc.w > 0.f) ? acc.w : 0.01f * acc.w;
    }
    __syncthreads();

    // h2 = lrelu(h1 @ wo2 + b2): 32 j4 x 8 kg of 16 k
    {
        const int j4 = tid & 31;
        const int kg = tid >> 5;
        const float4* w = wo24 + (size_t)(kg * 16) * 32 + j4;
        const float*  m = s_h1 + kg * 16;
        float4 acc = make_float4(0.f, 0.f, 0.f, 0.f);
#pragma unroll
        for (int k = 0; k < 16; ++k) {
            float4 v = __ldg(&w[(size_t)k * 32]);
            float  s = m[k];
            acc.x += s * v.x; acc.y += s * v.y; acc.z += s * v.z; acc.w += s * v.w;
        }
        __syncthreads();
        s_p[kg * 32 + j4] = acc;
    }
    __syncthreads();
    if (tid < 32) {
        float4 acc = __ldg(&b24[tid]);
#pragma unroll
        for (int g = 0; g < 8; ++g) {
            float4 v = s_p[g * 32 + tid];
            acc.x += v.x; acc.y += v.y; acc.z += v.z; acc.w += v.w;
        }
        s_h2[tid * 4 + 0] = (acc.x > 0.f) ? acc.x : 0.01f * acc.x;
        s_h2[tid * 4 + 1] = (acc.y > 0.f) ? acc.y : 0.01f * acc.y;
        s_h2[tid * 4 + 2] = (acc.z > 0.f) ? acc.z : 0.01f * acc.z;
        s_h2[tid * 4 + 3] = (acc.w > 0.f) ? acc.w : 0.01f * acc.w;
    }
    __syncthreads();

    // out = h2 @ wo3 + b3: 64 j4 x 4 kg of 32 k
    {
        const int j4 = tid & 63;
        const int kg = tid >> 6;
        const float4* w = wo34 + (size_t)(kg * 32) * 64 + j4;
        const float*  m = s_h2 + kg * 32;
        float4 acc = make_float4(0.f, 0.f, 0.f, 0.f);
#pragma unroll 8
        for (int k = 0; k < 32; ++k) {
            float4 v = __ldg(&w[(size_t)k * 64]);
            float  s = m[k];
            acc.x += s * v.x; acc.y += s * v.y; acc.z += s * v.z; acc.w += s * v.w;
        }
        __syncthreads();
        s_p[kg * 64 + j4] = acc;
    }
    __syncthreads();
    if (tid < 64) {
        float4 acc = __ldg(&b34[tid]);
#pragma unroll
        for (int g = 0; g < 4; ++g) {
            float4 v = s_p[g * 64 + tid];
            acc.x += v.x; acc.y += v.y; acc.z += v.z; acc.w += v.w;
        }
        out4[(size_t)b * 64 + tid] = acc;
    }
}

// ---------------------------------------------------------------------------
// Inputs: 0 feature, 1 lidar, 2 conv1_w, 3 conv2_w, 4 wq, 5 wk, 6 wv,
//         7 wo1, 8 b1, 9 wo2, 10 b2, 11 wo3, 12 b3
// ---------------------------------------------------------------------------
extern "C" void kernel_launch(void* const* d_in, const int* in_sizes, int n_in,
                              void* d_out, int out_size)
{
    const float4* lidar4 = (const float4*)d_in[1];
    const float4* wv4    = (const float4*)d_in[6];
    const float4* wo14   = (const float4*)d_in[7];
    const float4* b14    = (const float4*)d_in[8];
    const float4* wo24   = (const float4*)d_in[9];
    const float4* b24    = (const float4*)d_in[10];
    const float4* wo34   = (const float4*)d_in[11];
    const float4* b34    = (const float4*)d_in[12];
    float4* out4 = (float4*)d_out;

    lidar_reduce_kernel<<<REDUCE_BLOCKS + PF_BLOCKS, 256>>>(
        lidar4,
        (const char*)d_in[6], (const char*)d_in[7],
        (const char*)d_in[9], (const char*)d_in[11]);
    bins_h1_kernel<<<dim3(BATCH, 8), 256>>>(wv4, wo14);
    head_kernel<<<BATCH, 256>>>(b14, wo24, b24, wo34, b34, out4);
}